// round 16
// baseline (speedup 1.0000x reference)
#include <cuda_runtime.h>
#include <cuda_fp16.h>
#include <math.h>
#include <stdint.h>

#define B_ 32
#define C_ 64
#define H_ 64
#define W_ 64
#define E_ 8
#define HW_ (H_*W_)

// ---------------- scratch -------------------------------------------------
__device__ __align__(16) float g_S[B_*C_*9];
__device__ __align__(16) __half g_W[B_*64*64];    // prescaled W fp16 (single term)

// ---------------------------------------------------------------------------
// helpers
// ---------------------------------------------------------------------------
__device__ __forceinline__ uint32_t smem_u32(const void* p) {
    uint32_t a;
    asm("{ .reg .u64 t; cvta.to.shared.u64 t, %1; cvt.u32.u64 %0, t; }" : "=r"(a) : "l"(p));
    return a;
}
__device__ __forceinline__ void ldmat4(uint32_t* r, uint32_t addr) {
    asm volatile("ldmatrix.sync.aligned.m8n8.x4.shared.b16 {%0,%1,%2,%3}, [%4];"
        : "=r"(r[0]), "=r"(r[1]), "=r"(r[2]), "=r"(r[3]) : "r"(addr));
}
__device__ __forceinline__ void ldmat4t(uint32_t* r, uint32_t addr) {
    asm volatile("ldmatrix.sync.aligned.m8n8.x4.trans.shared.b16 {%0,%1,%2,%3}, [%4];"
        : "=r"(r[0]), "=r"(r[1]), "=r"(r[2]), "=r"(r[3]) : "r"(addr));
}
__device__ __forceinline__ void mma16816(float* d, const uint32_t* a, uint32_t b0, uint32_t b1) {
    asm volatile("mma.sync.aligned.m16n8k16.row.col.f32.f16.f16.f32 "
        "{%0,%1,%2,%3}, {%4,%5,%6,%7}, {%8,%9}, {%0,%1,%2,%3};"
        : "+f"(d[0]), "+f"(d[1]), "+f"(d[2]), "+f"(d[3])
        : "r"(a[0]), "r"(a[1]), "r"(a[2]), "r"(a[3]), "r"(b0), "r"(b1));
}
__device__ __forceinline__ uint32_t pack_h2(float a, float b) {
    __half2 h = __floats2half2_rn(a, b);
    return *(uint32_t*)&h;
}

// ---------------------------------------------------------------------------
// Kernel 1: window sums via inclusion-exclusion (R10/R14, proven 11.36us).
// ---------------------------------------------------------------------------
__global__ void __launch_bounds__(256) k_winsum(const float* __restrict__ x) {
    int bc  = blockIdx.x;
    int tid = threadIdx.x;
    const float4* img4 = (const float4*)(x + (size_t)bc * HW_);

    float4 v0 = img4[tid];
    float4 v1 = img4[tid + 256];
    float4 v2 = img4[tid + 512];
    float4 v3 = img4[tid + 768];

    float T = 0.f;
    float R0=0.f, R1=0.f, R2=0.f, R3=0.f;
    float C0=0.f, C1=0.f, C2=0.f, C3=0.f;

    float4 vv[4] = {v0, v1, v2, v3};
    int xq = tid & 15;
#pragma unroll
    for (int k = 0; k < 4; k++) {
        float4 v = vv[k];
        float s = (v.x + v.y) + (v.z + v.w);
        T += s;
        int y = (tid + k*256) >> 4;
        if (y == 0)       R0 += s;
        else if (y == 1)  R1 += s;
        else if (y == 62) R2 += s;
        else if (y == 63) R3 += s;
        if (xq == 0)       { C0 += v.x; C1 += v.y; }
        else if (xq == 15) { C2 += v.z; C3 += v.w; }
    }

    float a[9] = {T, R0, R1, R2, R3, C0, C1, C2, C3};
#pragma unroll
    for (int off = 16; off; off >>= 1)
#pragma unroll
        for (int k = 0; k < 9; k++)
            a[k] += __shfl_down_sync(0xffffffffu, a[k], off);

    __shared__ float sred[8][9];
    int warp = tid >> 5, lane = tid & 31;
    if (lane == 0)
#pragma unroll
        for (int k = 0; k < 9; k++) sred[warp][k] = a[k];
    __syncthreads();

    if (tid == 0) {
        float r[9];
#pragma unroll
        for (int k = 0; k < 9; k++) {
            float s = 0.f;
#pragma unroll
            for (int w = 0; w < 8; w++) s += sred[w][k];
            r[k] = s;
        }
        const float* img = x + (size_t)bc * HW_;
        const int yv[4] = {0, 1, 62, 63};
        float cv[4][4];
#pragma unroll
        for (int i = 0; i < 4; i++)
#pragma unroll
            for (int j = 0; j < 4; j++)
                cv[i][j] = img[yv[i]*64 + yv[j]];
        const int e0[3] = {2, 0, 0};
        const int e1[3] = {3, 3, 1};
        float* Sout = g_S + bc*9;
#pragma unroll
        for (int dy = 0; dy < 3; dy++) {
            int ya = e0[dy], yb = e1[dy];
#pragma unroll
            for (int dx = 0; dx < 3; dx++) {
                int xa = e0[dx], xb = e1[dx];
                Sout[dy*3+dx] = r[0]
                    - (r[1+ya] + r[1+yb]) - (r[5+xa] + r[5+xb])
                    + ((cv[ya][xa] + cv[ya][xb]) + (cv[yb][xa] + cv[yb][xb]));
            }
        }
    }
}

// ---------------------------------------------------------------------------
// Kernel 2: per-b gate + softmax + top-1 + prescaled fp16 W (single term).
// ---------------------------------------------------------------------------
__global__ void __launch_bounds__(256) k_prep(const float* __restrict__ gate_w,
                                              const float* __restrict__ gate_b,
                                              const float* __restrict__ expert_w,
                                              float* __restrict__ ew) {
    __shared__ float sg[E_];
    int b    = blockIdx.x;
    int tid  = threadIdx.x;
    int wid  = tid >> 5;
    int lane = tid & 31;

    {
        const float* Wg = gate_w + wid * (C_*9);
        const float* Sb = g_S    + b   * (C_*9);
        float g = 0.f;
#pragma unroll
        for (int i = 0; i < 18; i++) {
            int j = lane + i*32;
            g += Wg[j] * Sb[j];
        }
#pragma unroll
        for (int off = 16; off; off >>= 1)
            g += __shfl_down_sync(0xffffffffu, g, off);
        if (lane == 0) sg[wid] = g + 3844.0f * gate_b[wid];
    }
    __syncthreads();

    float gv[E_];
#pragma unroll
    for (int e = 0; e < E_; e++) gv[e] = sg[e];
    float m = gv[0];
#pragma unroll
    for (int e = 1; e < E_; e++) m = fmaxf(m, gv[e]);
    float ssum = 0.f;
#pragma unroll
    for (int e = 0; e < E_; e++) ssum += expf(gv[e] - m);
    float scale = 1.0f / ssum;
    int eidx = 7;
#pragma unroll
    for (int e = 7; e >= 0; e--) if (gv[e] == m) eidx = e;

    if (ew && tid < E_)
        ew[b*E_ + tid] = (tid == eidx) ? scale : 0.f;

    int f  = tid >> 2;
    int cq = tid & 3;
    const float4* Wp = (const float4*)(expert_w + ((size_t)eidx*C_ + f)*C_ + cq*16);
    uint32_t hi[8];
#pragma unroll
    for (int q = 0; q < 4; q++) {
        float4 v = Wp[q];
        hi[2*q]   = pack_h2(scale*v.x, scale*v.y);
        hi[2*q+1] = pack_h2(scale*v.z, scale*v.w);
    }
    uint4* dh = (uint4*)(g_W + ((size_t)b*64 + f) * 64 + cq*16);
    dh[0] = make_uint4(hi[0], hi[1], hi[2], hi[3]);
    dh[1] = make_uint4(hi[4], hi[5], hi[6], hi[7]);
}

// ---------------------------------------------------------------------------
// Kernel 3: pure fp16 HMMA GEMM, WIDE CTA tile 64f x 256hw.
// 256 threads = 8 warps, warp grid 2f x 4n, warp tile 32f x 64hw (proven).
// ---------------------------------------------------------------------------
#define TN 256                              // hw per CTA tile
#define WS_STRIDE 144
#define XS_STRIDE (TN*2 + 16)               // 528
#define WS_BYTES  (64*WS_STRIDE)            // 9216
#define XS_BYTES  (64*XS_STRIDE)            // 33792
#define SMEM_TOT  (WS_BYTES + XS_BYTES)     // 43008

__global__ void __launch_bounds__(256, 3) k_gemm(const float* __restrict__ x,
                                                 float* __restrict__ out) {
    extern __shared__ char smem[];
    uint32_t sb = smem_u32(smem);
    const uint32_t ws = sb;
    const uint32_t xs = sb + WS_BYTES;

    int tid  = threadIdx.x;
    int wid  = tid >> 5;
    int lane = tid & 31;
    int b    = blockIdx.y;
    int hw0  = blockIdx.x * TN;

    // ---- stage A: copy prepared W (64 rows x 128B) = 512 chunks / 256 thr
    {
        const uint4* Wp = (const uint4*)(g_W + (size_t)b * 64 * 64);
#pragma unroll
        for (int i = 0; i < 2; i++) {
            int id  = tid + i*256;
            int row = id >> 3, c16 = id & 7;
            uint4 v = Wp[id];
            asm volatile("st.shared.v4.b32 [%0], {%1,%2,%3,%4};" ::
                "r"(ws + (uint32_t)(row*WS_STRIDE + c16*16)),
                "r"(v.x), "r"(v.y), "r"(v.z), "r"(v.w) : "memory");
        }
    }

    // ---- stage B: x tile [64 c][256 hw] -> fp16. thread: c=tid>>2, 64 hw.
    {
        int c  = tid >> 2;
        int j0 = (tid & 3) * 64;
        const float4* Xp = (const float4*)(x + ((size_t)b*C_ + c)*HW_ + hw0 + j0);
        uint32_t dst = c*XS_STRIDE + j0*2;
#pragma unroll
        for (int h = 0; h < 8; h++) {
            float4 w0 = Xp[2*h], w1 = Xp[2*h+1];
            uint32_t h0 = pack_h2(w0.x, w0.y), h1 = pack_h2(w0.z, w0.w);
            uint32_t h2 = pack_h2(w1.x, w1.y), h3 = pack_h2(w1.z, w1.w);
            asm volatile("st.shared.v4.b32 [%0], {%1,%2,%3,%4};" ::
                "r"(xs + dst + h*16), "r"(h0), "r"(h1), "r"(h2), "r"(h3) : "memory");
        }
    }
    __syncthreads();

    // ---- compute: warp (wm, wn): f0 = wm*32, n0 = wn*64
    int wm = wid >> 2, wn = wid & 3;
    int f0 = wm * 32, n0 = wn * 64;

    float acc[2][8][4];
#pragma unroll
    for (int i = 0; i < 2; i++)
#pragma unroll
        for (int j = 0; j < 8; j++)
#pragma unroll
            for (int q = 0; q < 4; q++) acc[i][j][q] = 0.f;

    uint32_t a_lane = (uint32_t)((lane & 15) * WS_STRIDE + (lane >> 4) * 16);
    uint32_t b_lane = (uint32_t)((lane & 15) * XS_STRIDE + (lane >> 4) * 16);

#pragma unroll
    for (int k = 0; k < 4; k++) {
        uint32_t Ah[2][4], Bh[4][4];
#pragma unroll
        for (int mi = 0; mi < 2; mi++)
            ldmat4(Ah[mi], ws + (uint32_t)(f0 + mi*16)*WS_STRIDE + k*32 + a_lane);
#pragma unroll
        for (int nj = 0; nj < 4; nj++)
            ldmat4t(Bh[nj], xs + (uint32_t)(k*16)*XS_STRIDE + (uint32_t)(n0 + nj*16)*2 + b_lane);

#pragma unroll
        for (int mi = 0; mi < 2; mi++) {
#pragma unroll
            for (int nj = 0; nj < 4; nj++) {
                mma16816(acc[mi][nj*2],   Ah[mi], Bh[nj][0], Bh[nj][1]);
                mma16816(acc[mi][nj*2+1], Ah[mi], Bh[nj][2], Bh[nj][3]);
            }
        }
    }

    // ---- epilogue
    float* ob = out + (size_t)b * C_ * HW_ + hw0;
    int rrow = lane >> 2;
    int rcol = (lane & 3) * 2;
#pragma unroll
    for (int mi = 0; mi < 2; mi++) {
#pragma unroll
        for (int nj = 0; nj < 8; nj++) {
            float* p = ob + (size_t)(f0 + mi*16 + rrow) * HW_ + n0 + nj*8 + rcol;
            float2 w0; w0.x = acc[mi][nj][0]; w0.y = acc[mi][nj][1];
            float2 w1; w1.x = acc[mi][nj][2]; w1.y = acc[mi][nj][3];
            *(float2*)p = w0;
            *(float2*)(p + 8*HW_) = w1;
        }
    }
}

// ---------------------------------------------------------------------------
extern "C" void kernel_launch(void* const* d_in, const int* in_sizes, int n_in,
                              void* d_out, int out_size) {
    const float* x        = (const float*)d_in[0];
    const float* gate_w   = (const float*)d_in[1];
    const float* gate_b   = (const float*)d_in[2];
    const float* expert_w = (const float*)d_in[3];
    float* out = (float*)d_out;

    const int OUT_MAIN = B_*C_*HW_;
    float* ew = (out_size >= OUT_MAIN + B_*E_) ? (out + OUT_MAIN) : nullptr;

    cudaFuncSetAttribute(k_gemm, cudaFuncAttributeMaxDynamicSharedMemorySize, SMEM_TOT);

    k_winsum<<<B_*C_, 256>>>(x);
    k_prep<<<B_, 256>>>(gate_w, gate_b, expert_w, ew);
    k_gemm<<<dim3(HW_/TN, B_), 256, SMEM_TOT>>>(x, out);
}

// round 17
// speedup vs baseline: 1.1370x; 1.1370x over previous
#include <cuda_runtime.h>
#include <cuda_fp16.h>
#include <math.h>
#include <stdint.h>

#define B_ 32
#define C_ 64
#define H_ 64
#define W_ 64
#define E_ 8
#define HW_ (H_*W_)

// ---------------- scratch -------------------------------------------------
__device__ __align__(16) float g_S[B_*C_*9];
__device__ __align__(16) __half g_W[B_*64*64];    // prescaled W fp16 (single term)

// ---------------------------------------------------------------------------
// helpers
// ---------------------------------------------------------------------------
__device__ __forceinline__ uint32_t smem_u32(const void* p) {
    uint32_t a;
    asm("{ .reg .u64 t; cvta.to.shared.u64 t, %1; cvt.u32.u64 %0, t; }" : "=r"(a) : "l"(p));
    return a;
}
__device__ __forceinline__ void ldmat4(uint32_t* r, uint32_t addr) {
    asm volatile("ldmatrix.sync.aligned.m8n8.x4.shared.b16 {%0,%1,%2,%3}, [%4];"
        : "=r"(r[0]), "=r"(r[1]), "=r"(r[2]), "=r"(r[3]) : "r"(addr));
}
__device__ __forceinline__ void ldmat4t(uint32_t* r, uint32_t addr) {
    asm volatile("ldmatrix.sync.aligned.m8n8.x4.trans.shared.b16 {%0,%1,%2,%3}, [%4];"
        : "=r"(r[0]), "=r"(r[1]), "=r"(r[2]), "=r"(r[3]) : "r"(addr));
}
__device__ __forceinline__ void mma16816(float* d, const uint32_t* a, uint32_t b0, uint32_t b1) {
    asm volatile("mma.sync.aligned.m16n8k16.row.col.f32.f16.f16.f32 "
        "{%0,%1,%2,%3}, {%4,%5,%6,%7}, {%8,%9}, {%0,%1,%2,%3};"
        : "+f"(d[0]), "+f"(d[1]), "+f"(d[2]), "+f"(d[3])
        : "r"(a[0]), "r"(a[1]), "r"(a[2]), "r"(a[3]), "r"(b0), "r"(b1));
}
__device__ __forceinline__ uint32_t pack_h2(float a, float b) {
    __half2 h = __floats2half2_rn(a, b);
    return *(uint32_t*)&h;
}

// ---------------------------------------------------------------------------
// Kernel 1: window sums via inclusion-exclusion (R10/R14, proven).
// ---------------------------------------------------------------------------
__global__ void __launch_bounds__(256) k_winsum(const float* __restrict__ x) {
    int bc  = blockIdx.x;
    int tid = threadIdx.x;
    const float4* img4 = (const float4*)(x + (size_t)bc * HW_);

    float4 v0 = img4[tid];
    float4 v1 = img4[tid + 256];
    float4 v2 = img4[tid + 512];
    float4 v3 = img4[tid + 768];

    float T = 0.f;
    float R0=0.f, R1=0.f, R2=0.f, R3=0.f;
    float C0=0.f, C1=0.f, C2=0.f, C3=0.f;

    float4 vv[4] = {v0, v1, v2, v3};
    int xq = tid & 15;
#pragma unroll
    for (int k = 0; k < 4; k++) {
        float4 v = vv[k];
        float s = (v.x + v.y) + (v.z + v.w);
        T += s;
        int y = (tid + k*256) >> 4;
        if (y == 0)       R0 += s;
        else if (y == 1)  R1 += s;
        else if (y == 62) R2 += s;
        else if (y == 63) R3 += s;
        if (xq == 0)       { C0 += v.x; C1 += v.y; }
        else if (xq == 15) { C2 += v.z; C3 += v.w; }
    }

    float a[9] = {T, R0, R1, R2, R3, C0, C1, C2, C3};
#pragma unroll
    for (int off = 16; off; off >>= 1)
#pragma unroll
        for (int k = 0; k < 9; k++)
            a[k] += __shfl_down_sync(0xffffffffu, a[k], off);

    __shared__ float sred[8][9];
    int warp = tid >> 5, lane = tid & 31;
    if (lane == 0)
#pragma unroll
        for (int k = 0; k < 9; k++) sred[warp][k] = a[k];
    __syncthreads();

    if (tid == 0) {
        float r[9];
#pragma unroll
        for (int k = 0; k < 9; k++) {
            float s = 0.f;
#pragma unroll
            for (int w = 0; w < 8; w++) s += sred[w][k];
            r[k] = s;
        }
        const float* img = x + (size_t)bc * HW_;
        const int yv[4] = {0, 1, 62, 63};
        float cv[4][4];
#pragma unroll
        for (int i = 0; i < 4; i++)
#pragma unroll
            for (int j = 0; j < 4; j++)
                cv[i][j] = img[yv[i]*64 + yv[j]];
        const int e0[3] = {2, 0, 0};
        const int e1[3] = {3, 3, 1};
        float* Sout = g_S + bc*9;
#pragma unroll
        for (int dy = 0; dy < 3; dy++) {
            int ya = e0[dy], yb = e1[dy];
#pragma unroll
            for (int dx = 0; dx < 3; dx++) {
                int xa = e0[dx], xb = e1[dx];
                Sout[dy*3+dx] = r[0]
                    - (r[1+ya] + r[1+yb]) - (r[5+xa] + r[5+xb])
                    + ((cv[ya][xa] + cv[ya][xb]) + (cv[yb][xa] + cv[yb][xb]));
            }
        }
    }
}

// ---------------------------------------------------------------------------
// Kernel 2: per-b gate + softmax + top-1 + prescaled fp16 W (single term).
// ---------------------------------------------------------------------------
__global__ void __launch_bounds__(256) k_prep(const float* __restrict__ gate_w,
                                              const float* __restrict__ gate_b,
                                              const float* __restrict__ expert_w,
                                              float* __restrict__ ew) {
    __shared__ float sg[E_];
    int b    = blockIdx.x;
    int tid  = threadIdx.x;
    int wid  = tid >> 5;
    int lane = tid & 31;

    {
        const float* Wg = gate_w + wid * (C_*9);
        const float* Sb = g_S    + b   * (C_*9);
        float g = 0.f;
#pragma unroll
        for (int i = 0; i < 18; i++) {
            int j = lane + i*32;
            g += Wg[j] * Sb[j];
        }
#pragma unroll
        for (int off = 16; off; off >>= 1)
            g += __shfl_down_sync(0xffffffffu, g, off);
        if (lane == 0) sg[wid] = g + 3844.0f * gate_b[wid];
    }
    __syncthreads();

    float gv[E_];
#pragma unroll
    for (int e = 0; e < E_; e++) gv[e] = sg[e];
    float m = gv[0];
#pragma unroll
    for (int e = 1; e < E_; e++) m = fmaxf(m, gv[e]);
    float ssum = 0.f;
#pragma unroll
    for (int e = 0; e < E_; e++) ssum += expf(gv[e] - m);
    float scale = 1.0f / ssum;
    int eidx = 7;
#pragma unroll
    for (int e = 7; e >= 0; e--) if (gv[e] == m) eidx = e;

    if (ew && tid < E_)
        ew[b*E_ + tid] = (tid == eidx) ? scale : 0.f;

    int f  = tid >> 2;
    int cq = tid & 3;
    const float4* Wp = (const float4*)(expert_w + ((size_t)eidx*C_ + f)*C_ + cq*16);
    uint32_t hi[8];
#pragma unroll
    for (int q = 0; q < 4; q++) {
        float4 v = Wp[q];
        hi[2*q]   = pack_h2(scale*v.x, scale*v.y);
        hi[2*q+1] = pack_h2(scale*v.z, scale*v.w);
    }
    uint4* dh = (uint4*)(g_W + ((size_t)b*64 + f) * 64 + cq*16);
    dh[0] = make_uint4(hi[0], hi[1], hi[2], hi[3]);
    dh[1] = make_uint4(hi[4], hi[5], hi[6], hi[7]);
}

// ---------------------------------------------------------------------------
// Kernel 3: pure fp16 HMMA GEMM (R14, proven).  out = Wh @ fp16(x).
// CTA: 64 f x 128 hw, 4 warps of 32f x 64hw (warp grid 2f x 2n).
// ---------------------------------------------------------------------------
#define WS_STRIDE 144
#define XS_STRIDE 272
#define WS_BYTES  (64*WS_STRIDE)           // 9216
#define XS_BYTES  (64*XS_STRIDE)           // 17408
#define SMEM_TOT  (WS_BYTES + XS_BYTES)    // 26624

__global__ void __launch_bounds__(128, 5) k_gemm(const float* __restrict__ x,
                                                 float* __restrict__ out) {
    extern __shared__ char smem[];
    uint32_t sb = smem_u32(smem);
    const uint32_t ws = sb;
    const uint32_t xs = sb + WS_BYTES;

    int tid  = threadIdx.x;
    int wid  = tid >> 5;
    int lane = tid & 31;
    int b    = blockIdx.y;
    int hw0  = blockIdx.x * 128;

    // ---- stage A: copy prepared W (64 rows x 128B) = 512 chunks / 128 thr
    {
        const uint4* Wp = (const uint4*)(g_W + (size_t)b * 64 * 64);
#pragma unroll
        for (int i = 0; i < 4; i++) {
            int id  = tid + i*128;
            int row = id >> 3, c16 = id & 7;
            uint4 v = Wp[id];
            asm volatile("st.shared.v4.b32 [%0], {%1,%2,%3,%4};" ::
                "r"(ws + (uint32_t)(row*WS_STRIDE + c16*16)),
                "r"(v.x), "r"(v.y), "r"(v.z), "r"(v.w) : "memory");
        }
    }

    // ---- stage B: x tile [64 c][128 hw] -> fp16. thread: c=tid>>1, 64 hw.
    {
        int c  = tid >> 1;
        int j0 = (tid & 1) * 64;
        const float4* Xp = (const float4*)(x + ((size_t)b*C_ + c)*HW_ + hw0 + j0);
        uint32_t dst = c*XS_STRIDE + j0*2;
#pragma unroll
        for (int h = 0; h < 8; h++) {
            float4 w0 = Xp[2*h], w1 = Xp[2*h+1];
            uint32_t h0 = pack_h2(w0.x, w0.y), h1 = pack_h2(w0.z, w0.w);
            uint32_t h2 = pack_h2(w1.x, w1.y), h3 = pack_h2(w1.z, w1.w);
            asm volatile("st.shared.v4.b32 [%0], {%1,%2,%3,%4};" ::
                "r"(xs + dst + h*16), "r"(h0), "r"(h1), "r"(h2), "r"(h3) : "memory");
        }
    }
    __syncthreads();

    // ---- compute: warp (wm, wn): f0 = wm*32, n0 = wn*64
    int wm = wid >> 1, wn = wid & 1;
    int f0 = wm * 32, n0 = wn * 64;

    float acc[2][8][4];
#pragma unroll
    for (int i = 0; i < 2; i++)
#pragma unroll
        for (int j = 0; j < 8; j++)
#pragma unroll
            for (int q = 0; q < 4; q++) acc[i][j][q] = 0.f;

    uint32_t a_lane = (uint32_t)((lane & 15) * WS_STRIDE + (lane >> 4) * 16);
    uint32_t b_lane = (uint32_t)((lane & 15) * XS_STRIDE + (lane >> 4) * 16);

#pragma unroll
    for (int k = 0; k < 4; k++) {
        uint32_t Ah[2][4], Bh[4][4];
#pragma unroll
        for (int mi = 0; mi < 2; mi++)
            ldmat4(Ah[mi], ws + (uint32_t)(f0 + mi*16)*WS_STRIDE + k*32 + a_lane);
#pragma unroll
        for (int nj = 0; nj < 4; nj++)
            ldmat4t(Bh[nj], xs + (uint32_t)(k*16)*XS_STRIDE + (uint32_t)(n0 + nj*16)*2 + b_lane);

#pragma unroll
        for (int mi = 0; mi < 2; mi++) {
#pragma unroll
            for (int nj = 0; nj < 4; nj++) {
                mma16816(acc[mi][nj*2],   Ah[mi], Bh[nj][0], Bh[nj][1]);
                mma16816(acc[mi][nj*2+1], Ah[mi], Bh[nj][2], Bh[nj][3]);
            }
        }
    }

    // ---- epilogue
    float* ob = out + (size_t)b * C_ * HW_ + hw0;
    int rrow = lane >> 2;
    int rcol = (lane & 3) * 2;
#pragma unroll
    for (int mi = 0; mi < 2; mi++) {
#pragma unroll
        for (int nj = 0; nj < 8; nj++) {
            float* p = ob + (size_t)(f0 + mi*16 + rrow) * HW_ + n0 + nj*8 + rcol;
            float2 w0; w0.x = acc[mi][nj][0]; w0.y = acc[mi][nj][1];
            float2 w1; w1.x = acc[mi][nj][2]; w1.y = acc[mi][nj][3];
            *(float2*)p = w0;
            *(float2*)(p + 8*HW_) = w1;
        }
    }
}

// ---------------------------------------------------------------------------
extern "C" void kernel_launch(void* const* d_in, const int* in_sizes, int n_in,
                              void* d_out, int out_size) {
    const float* x        = (const float*)d_in[0];
    const float* gate_w   = (const float*)d_in[1];
    const float* gate_b   = (const float*)d_in[2];
    const float* expert_w = (const float*)d_in[3];
    float* out = (float*)d_out;

    const int OUT_MAIN = B_*C_*HW_;
    float* ew = (out_size >= OUT_MAIN + B_*E_) ? (out + OUT_MAIN) : nullptr;

    cudaFuncSetAttribute(k_gemm, cudaFuncAttributeMaxDynamicSharedMemorySize, SMEM_TOT);

    k_winsum<<<B_*C_, 256>>>(x);
    k_prep<<<B_, 256>>>(gate_w, gate_b, expert_w, ew);
    k_gemm<<<dim3(HW_/128, B_), 128, SMEM_TOT>>>(x, out);
}